// round 7
// baseline (speedup 1.0000x reference)
#include <cuda_runtime.h>

#define Bn 4
#define Pn 8
#define Vn 2048
#define En 2048
#define Fn 4096
#define NG (Bn * Pn)          // 32 (b,p) groups
#define CHAM 128              // chamfer blocks, equal edge share each
#define TPB 512               // 16 warps -> 4 warps/SMSP
#define VPT 4                 // 512*4 = 2048 verts (all of them) per block
#define EMAX 520              // max slice (<=512) + pad
#define BIGF 3.402823466e38f

__device__ float g_pmin[CHAM][2][Vn];        // per-block per-segment vertex mins
__device__ unsigned int g_gc[NG];            // per-group arrivals (monotonic)
__device__ float g_part_sum[NG], g_part_cnt[NG];
__device__ unsigned int g_counter;           // finalize events (monotonic)

// ---------------------------------------------------------------------------
__device__ __forceinline__ unsigned long long bcast2(float v) {
    unsigned long long r;
    asm("mov.b64 %0, {%1, %1};" : "=l"(r) : "f"(v));
    return r;
}

// d2[k] = px*x2[k] + py*y2[k] + c2[k] for k=0,1 ; fold into mins
__device__ __forceinline__ void edge2(float& m0, float& m1,
                                      unsigned long long pxx, unsigned long long pyy,
                                      unsigned long long x2, unsigned long long y2,
                                      unsigned long long c2)
{
    float d0, d1;
    asm("{\n\t"
        ".reg .b64 t;\n\t"
        "fma.rn.f32x2 t, %2, %3, %4;\n\t"
        "fma.rn.f32x2 t, %5, %6, t;\n\t"
        "mov.b64 {%0, %1}, t;\n\t"
        "}"
        : "=f"(d0), "=f"(d1)
        : "l"(pyy), "l"(y2), "l"(c2), "l"(pxx), "l"(x2));
    m0 = fminf(m0, d0);
    m1 = fminf(m1, d1);
}

// ---------------------------------------------------------------------------
// Blocks [0,128): chamfer, equal global edge share. Blocks [128,132): volume.
// ---------------------------------------------------------------------------
__global__ void __launch_bounds__(TPB)
fused_kernel(const float* __restrict__ xs,
             const float* __restrict__ pm,
             const float* __restrict__ em,
             const int*   __restrict__ lens,
             const void*  __restrict__ bmask,
             const int*   __restrict__ faces,
             const float* __restrict__ tv,
             float* __restrict__ out)
{
    const int bx  = blockIdx.x;
    const int tid = threadIdx.x;

    // =========================== VOLUME BLOCKS ============================
    if (bx >= CHAM) {
        __shared__ double sred[TPB];
        const int b = bx - CHAM;
        const float* base = xs + (size_t)b * Vn * 3;
        double acc = 0.0;
        for (int f = tid; f < Fn; f += TPB) {
            const int* fi = faces + ((size_t)b * Fn + f) * 3;
            const float* a0 = base + (size_t)fi[0] * 3;
            const float* a1 = base + (size_t)fi[1] * 3;
            const float* a2 = base + (size_t)fi[2] * 3;
            const float v0x = a0[0], v0y = a0[1], v0z = a0[2];
            const float v1x = a1[0], v1y = a1[1], v1z = a1[2];
            const float v2x = a2[0], v2y = a2[1], v2z = a2[2];
            const float cx = v0y * v1z - v0z * v1y;
            const float cy = v0z * v1x - v0x * v1z;
            const float cz = v0x * v1y - v0y * v1x;
            acc += (double)((cx * v2x + cy * v2y + cz * v2z) * (1.0f / 6.0f));
        }
        sred[tid] = acc;
        __syncthreads();
        #pragma unroll
        for (int s = TPB / 2; s >= 1; s >>= 1) {
            if (tid < s) sred[tid] += sred[tid + s];
            __syncthreads();
        }
        if (tid == 0) {
            float vols = fabsf((float)sred[0]);
            float d = vols - tv[b];
            out[4 + b] = d * d;
        }
        return;
    }

    // =========================== CHAMFER BLOCKS ===========================
    __shared__ __align__(16) float s_c[EMAX];
    __shared__ __align__(16) float s_x[EMAX];
    __shared__ __align__(16) float s_y[EMAX];
    __shared__ int   s_C[NG + 1];             // cumulative edge counts
    __shared__ float s_rs[TPB / 32], s_rc[TPB / 32];
    __shared__ int   s_klo[2], s_khi[2], s_fing[2];
    __shared__ int   s_lastg;

    // ---- schedule: prefix sum of lens ----
    if (tid < NG) s_C[tid + 1] = lens[tid];
    if (tid == 0) s_C[0] = 0;
    __syncthreads();
    if (tid == 0) {
        #pragma unroll
        for (int i = 1; i <= NG; ++i) s_C[i] += s_C[i - 1];
    }

    // ---- boundary_mask layout detection (first 4KB) ----
    unsigned int scan = 0;
    {
        const unsigned int* mw = (const unsigned int*)bmask;
        #pragma unroll
        for (int i = tid; i < 1024; i += TPB)
            scan |= (mw[i] & 0xFFFFFF00u);
    }
    const int mask_is_bytes = __syncthreads_or(scan != 0);  // barrier: s_C visible

    const int TE = s_C[NG];
    const int e0 = (int)(((long long)bx * TE) >> 7);        // /128
    const int e1 = (int)(((long long)(bx + 1) * TE) >> 7);

    // ---- process segments (<=2 groups spanned) ----
    int cov[2];
    int ncov = 0;
    int cur = e0;
    while (cur < e1 && ncov < 2) {
        int g = 0;
        while (s_C[g + 1] <= cur) ++g;            // uniform across block
        const int gend = (s_C[g + 1] < e1) ? s_C[g + 1] : e1;
        const int ls   = cur - s_C[g];
        const int llen = gend - cur;
        const int llen4 = (llen + 3) & ~3;

        __syncthreads();                          // protect smem reuse
        // preload + transform this edge sub-range
        const float2* embase = ((const float2*)em) + (size_t)g * En;
        for (int i = tid; i < llen; i += TPB) {
            float2 e = embase[ls + i];
            s_c[i] = fmaf(e.x, e.x, e.y * e.y);
            s_x[i] = -2.0f * e.x;
            s_y[i] = -2.0f * e.y;
        }
        for (int i = llen + tid; i < llen4; i += TPB) {
            s_c[i] = BIGF; s_x[i] = 0.0f; s_y[i] = 0.0f;
        }

        // projections for group g (all 2048 verts across block)
        const int b = g >> 3, p = g & 7;
        const float* M = pm + p * 12;
        float ppv[VPT];
        unsigned long long pxx[VPT], pyy[VPT];
        #pragma unroll
        for (int j = 0; j < VPT; ++j) {
            const int v = j * TPB + tid;
            const float* xv = xs + ((size_t)b * Vn + v) * 3;
            const float x = xv[0], y = xv[1], z = xv[2];
            const float q0 = M[0] * x + M[1] * y + M[2]  * z + M[3];
            const float q1 = M[4] * x + M[5] * y + M[6]  * z + M[7];
            const float q2 = M[8] * x + M[9] * y + M[10] * z + M[11];
            const float px = q0 / q2;
            const float py = q1 / q2;
            ppv[j] = fmaf(px, px, py * py);
            pxx[j] = bcast2(px);
            pyy[j] = bcast2(py);
        }
        __syncthreads();                          // edges ready

        // inner loop: 4 edges x 4 verts per iter, rotated prefetch
        float ma[VPT], mb[VPT], mc[VPT], md[VPT];
        #pragma unroll
        for (int j = 0; j < VPT; ++j) { ma[j]=BIGF; mb[j]=BIGF; mc[j]=BIGF; md[j]=BIGF; }

        const ulonglong2* pc  = (const ulonglong2*)s_c;
        const ulonglong2* pxv = (const ulonglong2*)s_x;
        const ulonglong2* pyv = (const ulonglong2*)s_y;
        const int NI = llen4 >> 2;

        if (NI > 0) {
            ulonglong2 c4 = pc[0], x4 = pxv[0], y4 = pyv[0];
            #pragma unroll 2
            for (int i = 1; i < NI; ++i) {
                const ulonglong2 cn = pc[i];
                const ulonglong2 xn = pxv[i];
                const ulonglong2 yn = pyv[i];
                #pragma unroll
                for (int j = 0; j < VPT; ++j) {
                    edge2(ma[j], mb[j], pxx[j], pyy[j], x4.x, y4.x, c4.x);
                    edge2(mc[j], md[j], pxx[j], pyy[j], x4.y, y4.y, c4.y);
                }
                c4 = cn; x4 = xn; y4 = yn;
            }
            #pragma unroll
            for (int j = 0; j < VPT; ++j) {
                edge2(ma[j], mb[j], pxx[j], pyy[j], x4.x, y4.x, c4.x);
                edge2(mc[j], md[j], pxx[j], pyy[j], x4.y, y4.y, c4.y);
            }
        }

        // per-vertex partial min (+|p|^2) -> own global slot
        #pragma unroll
        for (int j = 0; j < VPT; ++j) {
            const float dh = fminf(fminf(ma[j], mb[j]), fminf(mc[j], md[j])) + ppv[j];
            g_pmin[bx][ncov][j * TPB + tid] = dh;
        }
        cov[ncov++] = g;
        cur = gend;
    }

    __threadfence();
    __syncthreads();

    // ---- arrivals: tid0 computes contributor sets + increments counters ----
    if (tid == 0) {
        for (int c2 = 0; c2 < ncov; ++c2) {
            const int g = cov[c2];
            int klo = CHAM - 1, khi = 0, cnt = 0;
            for (int k = 0; k < CHAM; ++k) {
                const int ek0 = (int)(((long long)k * TE) >> 7);
                const int ek1 = (int)(((long long)(k + 1) * TE) >> 7);
                if (ek0 < s_C[g + 1] && ek1 > s_C[g]) {
                    ++cnt;
                    if (k < klo) klo = k;
                    if (k > khi) khi = k;
                }
            }
            s_klo[c2] = klo; s_khi[c2] = khi;
            const unsigned int old = atomicAdd(&g_gc[g], 1u);
            s_fing[c2] = (((old + 1u) % (unsigned int)cnt) == 0u) ? 1 : 0;
        }
    }
    __syncthreads();

    // ---- finalize groups we were elected for ----
    for (int c2 = 0; c2 < ncov; ++c2) {
        if (!s_fing[c2]) continue;
        const int g = cov[c2];
        __threadfence();

        float cs = 0.0f, cc = 0.0f;
        #pragma unroll
        for (int j = 0; j < VPT; ++j) {
            const int v = j * TPB + tid;
            float mn = BIGF;
            for (int k = s_klo[c2]; k <= s_khi[c2]; ++k) {
                const int ek0 = (int)(((long long)k * TE) >> 7);
                const int sseg = (ek0 >= s_C[g]) ? 0 : 1;
                mn = fminf(mn, __ldcg(&g_pmin[k][sseg][v]));
            }
            const int midx = g * Vn + v;
            float w;
            if (mask_is_bytes) w = (((const unsigned char*)bmask)[midx] != 0) ? 1.0f : 0.0f;
            else               w = (((const int*)bmask)[midx] != 0) ? 1.0f : 0.0f;
            cs = fmaf(w, mn, cs);
            cc += w;
        }

        #pragma unroll
        for (int off = 16; off >= 1; off >>= 1) {
            cs += __shfl_down_sync(0xffffffffu, cs, off);
            cc += __shfl_down_sync(0xffffffffu, cc, off);
        }
        const int wid = tid >> 5;
        if ((tid & 31) == 0) { s_rs[wid] = cs; s_rc[wid] = cc; }
        __syncthreads();

        if (tid == 0) {
            float ts = 0.0f, tc = 0.0f;
            #pragma unroll
            for (int i = 0; i < TPB / 32; ++i) { ts += s_rs[i]; tc += s_rc[i]; }
            g_part_sum[g] = ts;
            g_part_cnt[g] = tc;
            __threadfence();
            const unsigned int old = atomicAdd(&g_counter, 1u);
            s_lastg = (((old + 1u) & (NG - 1u)) == 0u) ? 1 : 0;
        }
        __syncthreads();

        if (s_lastg && tid < 32) {
            __threadfence();
            const int lane = tid;                 // lane = b*Pn + p
            const float su = __ldcg(&g_part_sum[lane]);
            const float ct = __ldcg(&g_part_cnt[lane]);
            float ppj = su / fmaxf(ct, 1.0f);
            #pragma unroll
            for (int off = 4; off >= 1; off >>= 1)
                ppj += __shfl_down_sync(0xffffffffu, ppj, off, 8);
            if ((lane & 7) == 0) out[lane >> 3] = ppj * (1.0f / Pn);
        }
        __syncthreads();
    }
}

// ---------------------------------------------------------------------------
extern "C" void kernel_launch(void* const* d_in, const int* in_sizes, int n_in,
                              void* d_out, int out_size)
{
    const float* xs    = (const float*)d_in[0];   // (4,2048,3)
    const float* pm    = (const float*)d_in[1];   // (8,3,4)
    const float* em    = (const float*)d_in[2];   // (4,8,2048,2)
    const int*   lens  = (const int*)  d_in[3];   // (4,8)
    const void*  bmask =               d_in[4];   // (4,8,2048) bool (auto-detected)
    const int*   faces = (const int*)  d_in[5];   // (4,4096,3)
    const float* tv    = (const float*)d_in[6];   // (4,)
    float* out = (float*)d_out;                   // [chamfer(4), vol_error(4)]

    fused_kernel<<<CHAM + Bn, TPB>>>(xs, pm, em, lens, bmask, faces, tv, out);
}

// round 8
// speedup vs baseline: 1.5644x; 1.5644x over previous
#include <cuda_runtime.h>

#define Bn 4
#define Pn 8
#define Vn 2048
#define En 2048
#define Fn 4096
#define TILES 4
#define TPB 256              // 8 warps -> 2 warps per SMSP
#define VPT 2                // vertices per thread -> 512 verts per block
#define CHAM_BLOCKS (Bn * Pn * TILES)   // 128
#define EMAX 2064            // En rounded up + prefetch pad (2 groups = 8 edges)
#define BIGF 3.402823466e38f

__device__ float g_part_sum[CHAM_BLOCKS];
__device__ float g_part_cnt[CHAM_BLOCKS];
__device__ unsigned int g_counter;   // never reset; +CHAM_BLOCKS per launch

// ---------------------------------------------------------------------------
// packed fp32x2 helpers (sm_103a FFMA2)
// ---------------------------------------------------------------------------
__device__ __forceinline__ unsigned long long bcast2(float v) {
    unsigned long long r;
    asm("mov.b64 %0, {%1, %1};" : "=l"(r) : "f"(v));
    return r;
}

// d2[k] = px*x2[k] + py*y2[k] + c2[k]  for k=0,1 ; fold into mins
__device__ __forceinline__ void edge2(float& m0, float& m1,
                                      unsigned long long pxx, unsigned long long pyy,
                                      unsigned long long x2, unsigned long long y2,
                                      unsigned long long c2)
{
    float d0, d1;
    asm("{\n\t"
        ".reg .b64 t;\n\t"
        "fma.rn.f32x2 t, %2, %3, %4;\n\t"
        "fma.rn.f32x2 t, %5, %6, t;\n\t"
        "mov.b64 {%0, %1}, t;\n\t"
        "}"
        : "=f"(d0), "=f"(d1)
        : "l"(pyy), "l"(y2), "l"(c2), "l"(pxx), "l"(x2));
    m0 = fminf(m0, d0);
    m1 = fminf(m1, d1);
}

// ---------------------------------------------------------------------------
// Single fused kernel. Blocks [0, 128): chamfer. Blocks [128, 132): volume.
// One block per SM, single wave. Last chamfer block finalizes.
// ---------------------------------------------------------------------------
__global__ void __launch_bounds__(TPB)
fused_kernel(const float* __restrict__ xs,
             const float* __restrict__ pm,
             const float* __restrict__ em,
             const int*   __restrict__ lens,
             const void*  __restrict__ bmask,
             const int*   __restrict__ faces,
             const float* __restrict__ tv,
             float* __restrict__ out)
{
    const int bx  = blockIdx.x;
    const int tid = threadIdx.x;

    // =========================== VOLUME BLOCKS ============================
    if (bx >= CHAM_BLOCKS) {
        __shared__ double sred[TPB];
        const int b = bx - CHAM_BLOCKS;
        const float* base = xs + (size_t)b * Vn * 3;
        double acc = 0.0;
        for (int f = tid; f < Fn; f += TPB) {
            const int* fi = faces + ((size_t)b * Fn + f) * 3;
            const float* a0 = base + (size_t)fi[0] * 3;
            const float* a1 = base + (size_t)fi[1] * 3;
            const float* a2 = base + (size_t)fi[2] * 3;
            const float v0x = a0[0], v0y = a0[1], v0z = a0[2];
            const float v1x = a1[0], v1y = a1[1], v1z = a1[2];
            const float v2x = a2[0], v2y = a2[1], v2z = a2[2];
            const float cx = v0y * v1z - v0z * v1y;
            const float cy = v0z * v1x - v0x * v1z;
            const float cz = v0x * v1y - v0y * v1x;
            acc += (double)((cx * v2x + cy * v2y + cz * v2z) * (1.0f / 6.0f));
        }
        sred[tid] = acc;
        __syncthreads();
        #pragma unroll
        for (int s = TPB / 2; s >= 1; s >>= 1) {
            if (tid < s) sred[tid] += sred[tid + s];
            __syncthreads();
        }
        if (tid == 0) {
            float vols = fabsf((float)sred[0]);
            float d = vols - tv[b];
            out[4 + b] = d * d;
        }
        return;
    }

    // =========================== CHAMFER BLOCKS ===========================
    // edge table SoA: c = |e|^2, x = -2ex, y = -2ey  (16B-aligned for LDS.128)
    __shared__ __align__(16) float s_c[EMAX];
    __shared__ __align__(16) float s_x[EMAX];
    __shared__ __align__(16) float s_y[EMAX];
    __shared__ float  s_rs[TPB / 32], s_rc[TPB / 32];
    __shared__ int    s_last;

    const int tile = bx & (TILES - 1);
    const int p    = (bx >> 2) & (Pn - 1);
    const int b    = bx >> 5;

    const int L    = lens[b * Pn + p];
    const int len4 = (L + 3) & ~3;

    // ---- preload + transform edge table [0, L), BIG-pad [L, len4+8) ----
    const float2* embase = (const float2*)(em + ((size_t)(b * Pn + p)) * En * 2);
    for (int i = tid; i < L; i += TPB) {
        float2 e = embase[i];
        s_c[i] = fmaf(e.x, e.x, e.y * e.y);
        s_x[i] = -2.0f * e.x;
        s_y[i] = -2.0f * e.y;
    }
    for (int i = L + tid; i < len4 + 8; i += TPB) {   // pad: kills tail + prefetch overrun
        s_c[i] = BIGF; s_x[i] = 0.0f; s_y[i] = 0.0f;
    }

    // ---- boundary_mask layout detection (first 4KB) ----
    // int32-widened bool: every byte at offset %4 != 0 is zero
    unsigned int scan = 0;
    {
        const unsigned int* mw = (const unsigned int*)bmask;
        #pragma unroll
        for (int i = tid; i < 1024; i += TPB)
            scan |= (mw[i] & 0xFFFFFF00u);
    }
    const int mask_is_bytes = __syncthreads_or(scan != 0);  // also the preload barrier

    // ---- per-thread vertex projections (VPT verts, stride TPB) ----
    const float* M = pm + p * 12;
    const int vbase = tile * (TPB * VPT);
    float px[VPT], py[VPT], ppv[VPT];
    unsigned long long pxx[VPT], pyy[VPT];
    #pragma unroll
    for (int j = 0; j < VPT; ++j) {
        const int v = vbase + j * TPB + tid;
        const float* xv = xs + ((size_t)b * Vn + v) * 3;
        const float x = xv[0], y = xv[1], z = xv[2];
        const float q0 = M[0] * x + M[1] * y + M[2]  * z + M[3];
        const float q1 = M[4] * x + M[5] * y + M[6]  * z + M[7];
        const float q2 = M[8] * x + M[9] * y + M[10] * z + M[11];
        px[j] = q0 / q2;
        py[j] = q1 / q2;
        ppv[j] = fmaf(px[j], px[j], py[j] * py[j]);
        pxx[j] = bcast2(px[j]);
        pyy[j] = bcast2(py[j]);
    }

    // ---- main loop: 4 edges x 2 verts per iter, 2-deep LDS prefetch ----
    const int NI = len4 >> 2;            // >= 256 since L >= 1024
    float ma[VPT], mb[VPT], mc[VPT], md[VPT];
    #pragma unroll
    for (int j = 0; j < VPT; ++j) { ma[j] = BIGF; mb[j] = BIGF; mc[j] = BIGF; md[j] = BIGF; }

    const ulonglong2* pc  = (const ulonglong2*)s_c;
    const ulonglong2* pxv = (const ulonglong2*)s_x;
    const ulonglong2* pyv = (const ulonglong2*)s_y;

    ulonglong2 cA = pc[0],  xA = pxv[0], yA = pyv[0];
    ulonglong2 cB = pc[1],  xB = pxv[1], yB = pyv[1];

    #pragma unroll 2
    for (int i = 0; i < NI; ++i) {
        // prefetch 2 groups ahead (pad guarantees in-bounds smem reads)
        const ulonglong2 cN = pc[i + 2];
        const ulonglong2 xN = pxv[i + 2];
        const ulonglong2 yN = pyv[i + 2];
        // compute on stage A
        #pragma unroll
        for (int j = 0; j < VPT; ++j) {
            edge2(ma[j], mb[j], pxx[j], pyy[j], xA.x, yA.x, cA.x);
            edge2(mc[j], md[j], pxx[j], pyy[j], xA.y, yA.y, cA.y);
        }
        // rotate (renamed away by unroll-2)
        cA = cB; xA = xB; yA = yB;
        cB = cN; xB = xN; yB = yN;
    }

    // ---- combine + boundary mask + local accumulation ----
    float cs = 0.0f, cc = 0.0f;
    #pragma unroll
    for (int j = 0; j < VPT; ++j) {
        const float dmin = fminf(fminf(ma[j], mb[j]), fminf(mc[j], md[j])) + ppv[j];
        const int v = vbase + j * TPB + tid;
        const int midx = (b * Pn + p) * Vn + v;
        float w;
        if (mask_is_bytes) w = (((const unsigned char*)bmask)[midx] != 0) ? 1.0f : 0.0f;
        else               w = (((const int*)bmask)[midx] != 0) ? 1.0f : 0.0f;
        cs = fmaf(w, dmin, cs);
        cc += w;
    }

    // ---- block reduction (deterministic fixed tree) ----
    #pragma unroll
    for (int off = 16; off >= 1; off >>= 1) {
        cs += __shfl_down_sync(0xffffffffu, cs, off);
        cc += __shfl_down_sync(0xffffffffu, cc, off);
    }
    const int wid = tid >> 5;
    if ((tid & 31) == 0) { s_rs[wid] = cs; s_rc[wid] = cc; }
    __syncthreads();

    if (tid == 0) {
        float ts = 0.0f, tc = 0.0f;
        #pragma unroll
        for (int i = 0; i < TPB / 32; ++i) { ts += s_rs[i]; tc += s_rc[i]; }
        const int slot = ((b * Pn + p) * TILES) + tile;
        g_part_sum[slot] = ts;
        g_part_cnt[slot] = tc;
        __threadfence();
        unsigned int old = atomicAdd(&g_counter, 1u);
        s_last = (((old + 1u) & (CHAM_BLOCKS - 1u)) == 0u) ? 1 : 0;
    }
    __syncthreads();

    // ---- last block finalizes chamfer means ----
    if (s_last && tid < 32) {
        __threadfence();
        const int lane = tid;                    // lane = b*Pn + p
        float s = 0.0f, c = 0.0f;
        #pragma unroll
        for (int t = 0; t < TILES; ++t) {
            s += g_part_sum[lane * TILES + t];
            c += g_part_cnt[lane * TILES + t];
        }
        float ppj = s / fmaxf(c, 1.0f);
        #pragma unroll
        for (int off = 4; off >= 1; off >>= 1)
            ppj += __shfl_down_sync(0xffffffffu, ppj, off, 8);
        if ((lane & 7) == 0) out[lane >> 3] = ppj * (1.0f / Pn);
    }
}

// ---------------------------------------------------------------------------
extern "C" void kernel_launch(void* const* d_in, const int* in_sizes, int n_in,
                              void* d_out, int out_size)
{
    const float* xs    = (const float*)d_in[0];   // (4,2048,3)
    const float* pm    = (const float*)d_in[1];   // (8,3,4)
    const float* em    = (const float*)d_in[2];   // (4,8,2048,2)
    const int*   lens  = (const int*)  d_in[3];   // (4,8)
    const void*  bmask =               d_in[4];   // (4,8,2048) bool (layout auto-detected)
    const int*   faces = (const int*)  d_in[5];   // (4,4096,3)
    const float* tv    = (const float*)d_in[6];   // (4,)
    float* out = (float*)d_out;                   // [chamfer(4), vol_error(4)]

    fused_kernel<<<CHAM_BLOCKS + Bn, TPB>>>(xs, pm, em, lens, bmask, faces, tv, out);
}

// round 11
// speedup vs baseline: 1.7208x; 1.1000x over previous
#include <cuda_runtime.h>

#define Bn 4
#define Pn 8
#define Vn 2048
#define En 2048
#define Fn 4096
#define TILES 4
#define TPB 512              // 16 warps; halves: tid<256 edges [0,S), tid>=256 [S,len4)
#define HALF 256
#define VPT 2                // verts per thread -> 512 verts per block
#define CHAM_BLOCKS (Bn * Pn * TILES)   // 128
#define EMAX 2052
#define BIGF 3.402823466e38f

__device__ float g_part_sum[CHAM_BLOCKS];
__device__ float g_part_cnt[CHAM_BLOCKS];
__device__ unsigned int g_counter;   // never reset; +CHAM_BLOCKS per launch

// ---------------------------------------------------------------------------
// packed fp32x2 helpers (sm_103a FFMA2)
// ---------------------------------------------------------------------------
__device__ __forceinline__ unsigned long long bcast2(float v) {
    unsigned long long r;
    asm("mov.b64 %0, {%1, %1};" : "=l"(r) : "f"(v));
    return r;
}

// d2[k] = px*x2[k] + py*y2[k] + c2[k]  for k=0,1 ; fold into mins
__device__ __forceinline__ void edge2(float& m0, float& m1,
                                      unsigned long long pxx, unsigned long long pyy,
                                      unsigned long long x2, unsigned long long y2,
                                      unsigned long long c2)
{
    float d0, d1;
    asm("{\n\t"
        ".reg .b64 t;\n\t"
        "fma.rn.f32x2 t, %2, %3, %4;\n\t"
        "fma.rn.f32x2 t, %5, %6, t;\n\t"
        "mov.b64 {%0, %1}, t;\n\t"
        "}"
        : "=f"(d0), "=f"(d1)
        : "l"(pyy), "l"(y2), "l"(c2), "l"(pxx), "l"(x2));
    m0 = fminf(m0, d0);
    m1 = fminf(m1, d1);
}

// ---------------------------------------------------------------------------
// Blocks [0, 128): chamfer (each block: 512 verts, two edge-halves across the
// two thread-halves). Blocks [128, 132): volume. One block/SM, single wave.
// ---------------------------------------------------------------------------
__global__ void __launch_bounds__(TPB)
fused_kernel(const float* __restrict__ xs,
             const float* __restrict__ pm,
             const float* __restrict__ em,
             const int*   __restrict__ lens,
             const void*  __restrict__ bmask,
             const int*   __restrict__ faces,
             const float* __restrict__ tv,
             float* __restrict__ out)
{
    const int bx  = blockIdx.x;
    const int tid = threadIdx.x;

    // =========================== VOLUME BLOCKS ============================
    if (bx >= CHAM_BLOCKS) {
        __shared__ double sred[TPB];
        const int b = bx - CHAM_BLOCKS;
        const float* base = xs + (size_t)b * Vn * 3;
        double acc = 0.0;
        for (int f = tid; f < Fn; f += TPB) {
            const int* fi = faces + ((size_t)b * Fn + f) * 3;
            const float* a0 = base + (size_t)fi[0] * 3;
            const float* a1 = base + (size_t)fi[1] * 3;
            const float* a2 = base + (size_t)fi[2] * 3;
            const float v0x = a0[0], v0y = a0[1], v0z = a0[2];
            const float v1x = a1[0], v1y = a1[1], v1z = a1[2];
            const float v2x = a2[0], v2y = a2[1], v2z = a2[2];
            const float cx = v0y * v1z - v0z * v1y;
            const float cy = v0z * v1x - v0x * v1z;
            const float cz = v0x * v1y - v0y * v1x;
            acc += (double)((cx * v2x + cy * v2y + cz * v2z) * (1.0f / 6.0f));
        }
        sred[tid] = acc;
        __syncthreads();
        #pragma unroll
        for (int s = TPB / 2; s >= 1; s >>= 1) {
            if (tid < s) sred[tid] += sred[tid + s];
            __syncthreads();
        }
        if (tid == 0) {
            float vols = fabsf((float)sred[0]);
            float d = vols - tv[b];
            out[4 + b] = d * d;
        }
        return;
    }

    // =========================== CHAMFER BLOCKS ===========================
    // edge table SoA: c = |e|^2, x = -2ex, y = -2ey  (16B-aligned for LDS.128)
    __shared__ __align__(16) float s_c[EMAX];
    __shared__ __align__(16) float s_x[EMAX];
    __shared__ __align__(16) float s_y[EMAX];
    __shared__ float  s_ex[HALF * VPT];            // half-1 per-vertex mins
    __shared__ float  s_rs[TPB / 32], s_rc[TPB / 32];
    __shared__ int    s_last;

    const int tile = bx & (TILES - 1);
    const int p    = (bx >> 2) & (Pn - 1);
    const int b    = bx >> 5;
    const int lane = tid & (HALF - 1);             // vertex slot within half
    const int halfid = tid >> 8;                   // 0 or 1: edge half

    const int L    = lens[b * Pn + p];
    const int len4 = (L + 3) & ~3;
    const int S    = ((L >> 1) + 3) & ~3;          // 4-edge-aligned split point

    // ---- preload + transform edge table (pairs of edges per float4) ----
    const float4* embase4 = (const float4*)(em + ((size_t)(b * Pn + p)) * En * 2);
    float2* c2p = (float2*)s_c;
    float2* x2p = (float2*)s_x;
    float2* y2p = (float2*)s_y;
    #pragma unroll
    for (int i = tid; i < En / 2; i += TPB) {
        float4 e4 = embase4[i];                 // ex0, ey0, ex1, ey1
        c2p[i] = make_float2(fmaf(e4.x, e4.x, e4.y * e4.y),
                             fmaf(e4.z, e4.z, e4.w * e4.w));
        x2p[i] = make_float2(-2.0f * e4.x, -2.0f * e4.z);
        y2p[i] = make_float2(-2.0f * e4.y, -2.0f * e4.w);
    }
    // BIG-pad [L, len4) so both halves run tail-free packed loops
    for (int i = L + tid; i < len4; i += TPB) {
        s_c[i] = BIGF; s_x[i] = 0.0f; s_y[i] = 0.0f;
    }

    // ---- boundary_mask layout detection (first 4KB) ----
    // int32-widened bool: every byte at offset %4 != 0 is zero
    unsigned int scan = 0;
    {
        const unsigned int* mw = (const unsigned int*)bmask;
        #pragma unroll
        for (int i = tid; i < 1024; i += TPB)
            scan |= (mw[i] & 0xFFFFFF00u);
    }
    const int mask_is_bytes = __syncthreads_or(scan != 0);  // also the preload barrier

    // ---- per-thread vertex projections (same verts in both halves) ----
    const float* M = pm + p * 12;
    const int vbase = tile * (HALF * VPT);
    float px[VPT], py[VPT], ppv[VPT];
    unsigned long long pxx[VPT], pyy[VPT];
    #pragma unroll
    for (int j = 0; j < VPT; ++j) {
        const int v = vbase + j * HALF + lane;
        const float* xv = xs + ((size_t)b * Vn + v) * 3;
        const float x = xv[0], y = xv[1], z = xv[2];
        const float q0 = M[0] * x + M[1] * y + M[2]  * z + M[3];
        const float q1 = M[4] * x + M[5] * y + M[6]  * z + M[7];
        const float q2 = M[8] * x + M[9] * y + M[10] * z + M[11];
        px[j] = q0 / q2;
        py[j] = q1 / q2;
        ppv[j] = fmaf(px[j], px[j], py[j] * py[j]);
        pxx[j] = bcast2(px[j]);
        pyy[j] = bcast2(py[j]);
    }

    // ---- main loop over this half's edge range (4 edges x 2 verts / iter) ----
    const int i0 = halfid ? (S >> 2) : 0;
    const int i1 = halfid ? (len4 >> 2) : (S >> 2);
    float ma[VPT], mb[VPT], mc[VPT], md[VPT];
    #pragma unroll
    for (int j = 0; j < VPT; ++j) { ma[j] = BIGF; mb[j] = BIGF; mc[j] = BIGF; md[j] = BIGF; }

    const ulonglong2* pc  = (const ulonglong2*)s_c;
    const ulonglong2* pxv = (const ulonglong2*)s_x;
    const ulonglong2* pyv = (const ulonglong2*)s_y;

    if (i1 > i0) {
        ulonglong2 c4 = pc[i0], x4 = pxv[i0], y4 = pyv[i0];
        #pragma unroll 2
        for (int i = i0 + 1; i < i1; ++i) {
            const ulonglong2 cn = pc[i];
            const ulonglong2 xn = pxv[i];
            const ulonglong2 yn = pyv[i];
            #pragma unroll
            for (int j = 0; j < VPT; ++j) {
                edge2(ma[j], mb[j], pxx[j], pyy[j], x4.x, y4.x, c4.x);
                edge2(mc[j], md[j], pxx[j], pyy[j], x4.y, y4.y, c4.y);
            }
            c4 = cn; x4 = xn; y4 = yn;
        }
        #pragma unroll
        for (int j = 0; j < VPT; ++j) {
            edge2(ma[j], mb[j], pxx[j], pyy[j], x4.x, y4.x, c4.x);
            edge2(mc[j], md[j], pxx[j], pyy[j], x4.y, y4.y, c4.y);
        }
    }

    // ---- half-1 publishes its per-vertex mins; half-0 combines ----
    float dh[VPT];
    #pragma unroll
    for (int j = 0; j < VPT; ++j)
        dh[j] = fminf(fminf(ma[j], mb[j]), fminf(mc[j], md[j]));

    if (halfid) {
        #pragma unroll
        for (int j = 0; j < VPT; ++j) s_ex[j * HALF + lane] = dh[j];
    }
    __syncthreads();

    float cs = 0.0f, cc = 0.0f;
    if (!halfid) {
        #pragma unroll
        for (int j = 0; j < VPT; ++j) {
            const float dmin = fminf(dh[j], s_ex[j * HALF + lane]) + ppv[j];
            const int v = vbase + j * HALF + lane;
            const int midx = (b * Pn + p) * Vn + v;
            float w;
            if (mask_is_bytes) w = (((const unsigned char*)bmask)[midx] != 0) ? 1.0f : 0.0f;
            else               w = (((const int*)bmask)[midx] != 0) ? 1.0f : 0.0f;
            cs = fmaf(w, dmin, cs);
            cc += w;
        }
    }

    // ---- block reduction (deterministic fixed tree; half-1 contributes 0) ----
    #pragma unroll
    for (int off = 16; off >= 1; off >>= 1) {
        cs += __shfl_down_sync(0xffffffffu, cs, off);
        cc += __shfl_down_sync(0xffffffffu, cc, off);
    }
    const int wid = tid >> 5;
    if ((tid & 31) == 0) { s_rs[wid] = cs; s_rc[wid] = cc; }
    __syncthreads();

    if (tid == 0) {
        float ts = 0.0f, tc = 0.0f;
        #pragma unroll
        for (int i = 0; i < TPB / 32; ++i) { ts += s_rs[i]; tc += s_rc[i]; }
        const int slot = ((b * Pn + p) * TILES) + tile;
        g_part_sum[slot] = ts;
        g_part_cnt[slot] = tc;
        __threadfence();
        unsigned int old = atomicAdd(&g_counter, 1u);
        s_last = (((old + 1u) & (CHAM_BLOCKS - 1u)) == 0u) ? 1 : 0;
    }
    __syncthreads();

    // ---- last block finalizes chamfer means ----
    if (s_last && tid < 32) {
        __threadfence();
        const int ln = tid;                      // ln = b*Pn + p
        float s = 0.0f, c = 0.0f;
        #pragma unroll
        for (int t = 0; t < TILES; ++t) {
            s += g_part_sum[ln * TILES + t];
            c += g_part_cnt[ln * TILES + t];
        }
        float ppj = s / fmaxf(c, 1.0f);
        #pragma unroll
        for (int off = 4; off >= 1; off >>= 1)
            ppj += __shfl_down_sync(0xffffffffu, ppj, off, 8);
        if ((ln & 7) == 0) out[ln >> 3] = ppj * (1.0f / Pn);
    }
}

// ---------------------------------------------------------------------------
extern "C" void kernel_launch(void* const* d_in, const int* in_sizes, int n_in,
                              void* d_out, int out_size)
{
    const float* xs    = (const float*)d_in[0];   // (4,2048,3)
    const float* pm    = (const float*)d_in[1];   // (8,3,4)
    const float* em    = (const float*)d_in[2];   // (4,8,2048,2)
    const int*   lens  = (const int*)  d_in[3];   // (4,8)
    const void*  bmask =               d_in[4];   // (4,8,2048) bool (layout auto-detected)
    const int*   faces = (const int*)  d_in[5];   // (4,4096,3)
    const float* tv    = (const float*)d_in[6];   // (4,)
    float* out = (float*)d_out;                   // [chamfer(4), vol_error(4)]

    fused_kernel<<<CHAM_BLOCKS + Bn, TPB>>>(xs, pm, em, lens, bmask, faces, tv, out);
}

// round 12
// speedup vs baseline: 1.7232x; 1.0014x over previous
#include <cuda_runtime.h>

#define Bn 4
#define Pn 8
#define Vn 2048
#define En 2048
#define Fn 4096
#define TILES 4
#define TPB 512              // 16 warps; tid<256: edges [0,S); tid>=256: [S,len4)
#define HALF 256
#define VPT 2                // compacted-vert slots per thread
#define CHAM_BLOCKS (Bn * Pn * TILES)   // 128
#define EMAX 2052
#define BIGF 3.402823466e38f

__device__ float g_part_sum[CHAM_BLOCKS];
__device__ float g_part_cnt[CHAM_BLOCKS];
__device__ unsigned int g_counter;   // never reset; +CHAM_BLOCKS per launch

// ---------------------------------------------------------------------------
// packed fp32x2 helpers (sm_103a FFMA2)
// ---------------------------------------------------------------------------
__device__ __forceinline__ unsigned long long bcast2(float v) {
    unsigned long long r;
    asm("mov.b64 %0, {%1, %1};" : "=l"(r) : "f"(v));
    return r;
}

// d2[k] = px*x2[k] + py*y2[k] + c2[k]  for k=0,1 ; fold into mins
__device__ __forceinline__ void edge2(float& m0, float& m1,
                                      unsigned long long pxx, unsigned long long pyy,
                                      unsigned long long x2, unsigned long long y2,
                                      unsigned long long c2)
{
    float d0, d1;
    asm("{\n\t"
        ".reg .b64 t;\n\t"
        "fma.rn.f32x2 t, %2, %3, %4;\n\t"
        "fma.rn.f32x2 t, %5, %6, t;\n\t"
        "mov.b64 {%0, %1}, t;\n\t"
        "}"
        : "=f"(d0), "=f"(d1)
        : "l"(pyy), "l"(y2), "l"(c2), "l"(pxx), "l"(x2));
    m0 = fminf(m0, d0);
    m1 = fminf(m1, d1);
}

// ---------------------------------------------------------------------------
// Blocks [0,128): chamfer (512 verts compacted to masked-only; two edge-halves
// across thread-halves; warp-major slots so empty warps skip the loop).
// Blocks [128,132): volume. One block/SM, single wave.
// ---------------------------------------------------------------------------
__global__ void __launch_bounds__(TPB)
fused_kernel(const float* __restrict__ xs,
             const float* __restrict__ pm,
             const float* __restrict__ em,
             const int*   __restrict__ lens,
             const void*  __restrict__ bmask,
             const int*   __restrict__ faces,
             const float* __restrict__ tv,
             float* __restrict__ out)
{
    const int bx  = blockIdx.x;
    const int tid = threadIdx.x;

    // =========================== VOLUME BLOCKS ============================
    if (bx >= CHAM_BLOCKS) {
        __shared__ double sred[TPB];
        const int b = bx - CHAM_BLOCKS;
        const float* base = xs + (size_t)b * Vn * 3;
        double acc = 0.0;
        for (int f = tid; f < Fn; f += TPB) {
            const int* fi = faces + ((size_t)b * Fn + f) * 3;
            const float* a0 = base + (size_t)fi[0] * 3;
            const float* a1 = base + (size_t)fi[1] * 3;
            const float* a2 = base + (size_t)fi[2] * 3;
            const float v0x = a0[0], v0y = a0[1], v0z = a0[2];
            const float v1x = a1[0], v1y = a1[1], v1z = a1[2];
            const float v2x = a2[0], v2y = a2[1], v2z = a2[2];
            const float cx = v0y * v1z - v0z * v1y;
            const float cy = v0z * v1x - v0x * v1z;
            const float cz = v0x * v1y - v0y * v1x;
            acc += (double)((cx * v2x + cy * v2y + cz * v2z) * (1.0f / 6.0f));
        }
        sred[tid] = acc;
        __syncthreads();
        #pragma unroll
        for (int s = TPB / 2; s >= 1; s >>= 1) {
            if (tid < s) sred[tid] += sred[tid + s];
            __syncthreads();
        }
        if (tid == 0) {
            float vols = fabsf((float)sred[0]);
            float d = vols - tv[b];
            out[4 + b] = d * d;
        }
        return;
    }

    // =========================== CHAMFER BLOCKS ===========================
    __shared__ __align__(16) float s_c[EMAX];
    __shared__ __align__(16) float s_x[EMAX];
    __shared__ __align__(16) float s_y[EMAX];
    __shared__ short s_vidx[TPB];                  // compacted local vert ids
    __shared__ int   s_wofs[17];                   // warp prefix offsets
    __shared__ float s_ex[TPB];                    // half-1 per-slot mins
    __shared__ float s_rs[TPB / 32], s_rc[TPB / 32];
    __shared__ int   s_last;

    const int tile   = bx & (TILES - 1);
    const int p      = (bx >> 2) & (Pn - 1);
    const int b      = bx >> 5;
    const int lane31 = tid & 31;
    const int wid    = tid >> 5;
    const int halfid = tid >> 8;                   // 0/1 edge half
    const int winh   = (tid & (HALF - 1)) >> 5;    // warp index within half (0..7)

    const int L    = lens[b * Pn + p];
    const int len4 = (L + 3) & ~3;
    const int S    = ((L >> 1) + 3) & ~3;          // 4-edge-aligned split point

    // ---- preload + transform edge table ----
    const float4* embase4 = (const float4*)(em + ((size_t)(b * Pn + p)) * En * 2);
    float2* c2p = (float2*)s_c;
    float2* x2p = (float2*)s_x;
    float2* y2p = (float2*)s_y;
    #pragma unroll
    for (int i = tid; i < En / 2; i += TPB) {
        float4 e4 = embase4[i];                 // ex0, ey0, ex1, ey1
        c2p[i] = make_float2(fmaf(e4.x, e4.x, e4.y * e4.y),
                             fmaf(e4.z, e4.z, e4.w * e4.w));
        x2p[i] = make_float2(-2.0f * e4.x, -2.0f * e4.z);
        y2p[i] = make_float2(-2.0f * e4.y, -2.0f * e4.w);
    }
    for (int i = L + tid; i < len4; i += TPB) {    // BIG pad -> tail-free loops
        s_c[i] = BIGF; s_x[i] = 0.0f; s_y[i] = 0.0f;
    }

    // ---- boundary_mask layout detection (first 4KB) ----
    unsigned int scan = 0;
    {
        const unsigned int* mw = (const unsigned int*)bmask;
        #pragma unroll
        for (int i = tid; i < 1024; i += TPB)
            scan |= (mw[i] & 0xFFFFFF00u);
    }
    const int mask_is_bytes = __syncthreads_or(scan != 0);  // also preload barrier

    // ---- deterministic compaction of this block's 512 verts (masked only) ----
    const int vbase = tile * TPB;                  // 512 verts per block
    const int midx0 = (b * Pn + p) * Vn + vbase + tid;
    bool m;
    if (mask_is_bytes) m = (((const unsigned char*)bmask)[midx0] != 0);
    else               m = (((const int*)bmask)[midx0] != 0);
    const unsigned int bal = __ballot_sync(0xffffffffu, m);
    if (lane31 == 0) s_wofs[wid + 1] = __popc(bal);
    __syncthreads();
    if (tid == 0) {
        s_wofs[0] = 0;
        #pragma unroll
        for (int i = 1; i <= 16; ++i) s_wofs[i] += s_wofs[i - 1];
    }
    __syncthreads();
    if (m) {
        const int pos = s_wofs[wid] + __popc(bal & ((1u << lane31) - 1u));
        s_vidx[pos] = (short)tid;                  // local vert id, order fixed by tid
    }
    const int NC = s_wofs[16];
    __syncthreads();

    // ---- warp-major slot assignment: warp owns 64 contiguous slots ----
    const int sbase = winh * 64 + lane31;          // slots sbase, sbase+32
    const bool wactive = (NC > winh * 64);         // uniform per warp

    // ---- projections for owned compacted slots ----
    const float* M = pm + p * 12;
    int   slot[VPT];
    float px[VPT], py[VPT], ppv[VPT];
    unsigned long long pxx[VPT], pyy[VPT];
    #pragma unroll
    for (int j = 0; j < VPT; ++j) {
        slot[j] = sbase + j * 32;
        float x = 0.0f, y = 0.0f, z = 0.0f;
        if (slot[j] < NC) {
            const int v = vbase + (int)s_vidx[slot[j]];
            const float* xv = xs + ((size_t)b * Vn + v) * 3;
            x = xv[0]; y = xv[1]; z = xv[2];
        }
        const float q0 = M[0] * x + M[1] * y + M[2]  * z + M[3];
        const float q1 = M[4] * x + M[5] * y + M[6]  * z + M[7];
        const float q2 = M[8] * x + M[9] * y + M[10] * z + M[11];
        px[j] = q0 / q2;
        py[j] = q1 / q2;
        ppv[j] = fmaf(px[j], px[j], py[j] * py[j]);
        pxx[j] = bcast2(px[j]);
        pyy[j] = bcast2(py[j]);
    }

    // ---- edge loop over this half's range (only warps with live slots) ----
    float ma[VPT], mb[VPT], mc[VPT], md[VPT];
    #pragma unroll
    for (int j = 0; j < VPT; ++j) { ma[j] = BIGF; mb[j] = BIGF; mc[j] = BIGF; md[j] = BIGF; }

    if (wactive) {
        const int i0 = halfid ? (S >> 2) : 0;
        const int i1 = halfid ? (len4 >> 2) : (S >> 2);
        const ulonglong2* pc  = (const ulonglong2*)s_c;
        const ulonglong2* pxv = (const ulonglong2*)s_x;
        const ulonglong2* pyv = (const ulonglong2*)s_y;
        if (i1 > i0) {
            ulonglong2 c4 = pc[i0], x4 = pxv[i0], y4 = pyv[i0];
            #pragma unroll 2
            for (int i = i0 + 1; i < i1; ++i) {
                const ulonglong2 cn = pc[i];
                const ulonglong2 xn = pxv[i];
                const ulonglong2 yn = pyv[i];
                #pragma unroll
                for (int j = 0; j < VPT; ++j) {
                    edge2(ma[j], mb[j], pxx[j], pyy[j], x4.x, y4.x, c4.x);
                    edge2(mc[j], md[j], pxx[j], pyy[j], x4.y, y4.y, c4.y);
                }
                c4 = cn; x4 = xn; y4 = yn;
            }
            #pragma unroll
            for (int j = 0; j < VPT; ++j) {
                edge2(ma[j], mb[j], pxx[j], pyy[j], x4.x, y4.x, c4.x);
                edge2(mc[j], md[j], pxx[j], pyy[j], x4.y, y4.y, c4.y);
            }
        }
    }

    // ---- half-1 publishes per-slot mins; half-0 combines ----
    float dh[VPT];
    #pragma unroll
    for (int j = 0; j < VPT; ++j)
        dh[j] = fminf(fminf(ma[j], mb[j]), fminf(mc[j], md[j]));

    if (halfid && wactive) {
        #pragma unroll
        for (int j = 0; j < VPT; ++j) s_ex[slot[j]] = dh[j];
    }
    __syncthreads();

    float cs = 0.0f, cc = 0.0f;
    if (!halfid && wactive) {
        #pragma unroll
        for (int j = 0; j < VPT; ++j) {
            if (slot[j] < NC) {
                const float dmin = fminf(dh[j], s_ex[slot[j]]) + ppv[j];
                cs += dmin;
                cc += 1.0f;
            }
        }
    }

    // ---- block reduction (deterministic fixed tree) ----
    #pragma unroll
    for (int off = 16; off >= 1; off >>= 1) {
        cs += __shfl_down_sync(0xffffffffu, cs, off);
        cc += __shfl_down_sync(0xffffffffu, cc, off);
    }
    if (lane31 == 0) { s_rs[wid] = cs; s_rc[wid] = cc; }
    __syncthreads();

    if (tid == 0) {
        float ts = 0.0f, tc = 0.0f;
        #pragma unroll
        for (int i = 0; i < TPB / 32; ++i) { ts += s_rs[i]; tc += s_rc[i]; }
        const int slotg = ((b * Pn + p) * TILES) + tile;
        g_part_sum[slotg] = ts;
        g_part_cnt[slotg] = tc;
        __threadfence();
        unsigned int old = atomicAdd(&g_counter, 1u);
        s_last = (((old + 1u) & (CHAM_BLOCKS - 1u)) == 0u) ? 1 : 0;
    }
    __syncthreads();

    // ---- last block finalizes chamfer means ----
    if (s_last && tid < 32) {
        __threadfence();
        const int ln = tid;                      // ln = b*Pn + p
        float s = 0.0f, c = 0.0f;
        #pragma unroll
        for (int t = 0; t < TILES; ++t) {
            s += g_part_sum[ln * TILES + t];
            c += g_part_cnt[ln * TILES + t];
        }
        float ppj = s / fmaxf(c, 1.0f);
        #pragma unroll
        for (int off = 4; off >= 1; off >>= 1)
            ppj += __shfl_down_sync(0xffffffffu, ppj, off, 8);
        if ((ln & 7) == 0) out[ln >> 3] = ppj * (1.0f / Pn);
    }
}

// ---------------------------------------------------------------------------
extern "C" void kernel_launch(void* const* d_in, const int* in_sizes, int n_in,
                              void* d_out, int out_size)
{
    const float* xs    = (const float*)d_in[0];   // (4,2048,3)
    const float* pm    = (const float*)d_in[1];   // (8,3,4)
    const float* em    = (const float*)d_in[2];   // (4,8,2048,2)
    const int*   lens  = (const int*)  d_in[3];   // (4,8)
    const void*  bmask =               d_in[4];   // (4,8,2048) bool (auto-detected)
    const int*   faces = (const int*)  d_in[5];   // (4,4096,3)
    const float* tv    = (const float*)d_in[6];   // (4,)
    float* out = (float*)d_out;                   // [chamfer(4), vol_error(4)]

    fused_kernel<<<CHAM_BLOCKS + Bn, TPB>>>(xs, pm, em, lens, bmask, faces, tv, out);
}